// round 3
// baseline (speedup 1.0000x reference)
#include <cuda_runtime.h>
#include <cuda_fp16.h>
#include <math.h>

#define Bn 8
#define Nn 4096
#define En 131072
#define ALPHA 0.2f

// ---------------- device scratch (no allocations allowed) ----------------
__device__ __half d_WhH[Bn * Nn * 64];   // 4 MB, (b*N+n)*64+f, fp16
__device__ float  d_ssrcT[Nn * Bn];      // [n][b]
__device__ float  d_sdstT[Nn * Bn];      // [n][b]
__device__ int    d_counts[Nn];          // zero at load; re-zeroed by k_scan each launch
__device__ int    d_offsets[Nn + 1];
__device__ int    d_cursor[Nn];
__device__ int    d_dstP[En];            // dst in CSR order
__device__ float  d_exP[En * Bn];        // exp(e) per edge per batch, CSR order

// ---------------- kernel 1: gemm (blocks 0..255) + degree count (blocks 256..383) ----------------
__global__ void __launch_bounds__(256) k_gemm_count(const float* __restrict__ h,
                                                    const float* __restrict__ W,
                                                    const float* __restrict__ a,
                                                    const int* __restrict__ src) {
    int t = threadIdx.x;
    if (blockIdx.x >= 256) {
        // degree count: 128 blocks x 256 threads x 4 edges
        int base = (blockIdx.x - 256) * 1024 + t;
        #pragma unroll
        for (int k = 0; k < 4; k++)
            atomicAdd(&d_counts[src[base + k * 256]], 1);
        return;
    }

    __shared__ float sW[64 * 64];
    __shared__ float sh[4][64];
    __shared__ float red1[8], red2[8];

    for (int i = t; i < 4096; i += 256) sW[i] = W[i];
    __syncthreads();

    int g = t >> 6;        // group 0..3 (one row each)
    int o = t & 63;        // output feature
    float a1r = a[o];
    float a2r = a[64 + o];
    int base = blockIdx.x * 128;

    for (int r0 = 0; r0 < 128; r0 += 4) {
        int row = base + r0 + g;   // b*N+n
        sh[g][o] = h[row * 64 + o];
        __syncthreads();
        float acc = 0.f;
        #pragma unroll
        for (int f = 0; f < 64; f++) acc = fmaf(sh[g][f], sW[f * 64 + o], acc);
        d_WhH[row * 64 + o] = __float2half(acc);

        float p1 = acc * a1r;
        float p2 = acc * a2r;
        #pragma unroll
        for (int off = 16; off; off >>= 1) {
            p1 += __shfl_xor_sync(0xffffffffu, p1, off);
            p2 += __shfl_xor_sync(0xffffffffu, p2, off);
        }
        int w = t >> 5;
        if ((t & 31) == 0) { red1[w] = p1; red2[w] = p2; }
        __syncthreads();
        if ((t & 63) == 0) {
            int b = row >> 12;
            int n = row & 4095;
            d_ssrcT[n * 8 + b] = red1[g * 2] + red1[g * 2 + 1];
            d_sdstT[n * 8 + b] = red2[g * 2] + red2[g * 2 + 1];
        }
        __syncthreads();
    }
}

// ---------------- scan: offsets from counts, then re-zero counts ----------------
__global__ void __launch_bounds__(1024) k_scan() {
    __shared__ int warp_sums[32];
    int t = threadIdx.x;
    int lane = t & 31, wid = t >> 5;
    int4 c = reinterpret_cast<const int4*>(d_counts)[t];
    reinterpret_cast<int4*>(d_counts)[t] = make_int4(0, 0, 0, 0);  // ready for next launch
    int sum = c.x + c.y + c.z + c.w;

    int v = sum;
    #pragma unroll
    for (int off = 1; off < 32; off <<= 1) {
        int u = __shfl_up_sync(0xffffffffu, v, off);
        if (lane >= off) v += u;
    }
    if (lane == 31) warp_sums[wid] = v;
    __syncthreads();
    if (wid == 0) {
        int w = warp_sums[lane];
        #pragma unroll
        for (int off = 1; off < 32; off <<= 1) {
            int u = __shfl_up_sync(0xffffffffu, w, off);
            if (lane >= off) w += u;
        }
        warp_sums[lane] = w;
    }
    __syncthreads();

    int base = (v - sum) + (wid ? warp_sums[wid - 1] : 0);
    int o0 = base;
    int o1 = base + c.x;
    int o2 = o1 + c.y;
    int o3 = o2 + c.z;
    d_offsets[4 * t + 0] = o0;  d_cursor[4 * t + 0] = o0;
    d_offsets[4 * t + 1] = o1;  d_cursor[4 * t + 1] = o1;
    d_offsets[4 * t + 2] = o2;  d_cursor[4 * t + 2] = o2;
    d_offsets[4 * t + 3] = o3;  d_cursor[4 * t + 3] = o3;
    if (t == 1023) d_offsets[Nn] = warp_sums[31];
}

// ---------------- scatter: permute + compute exp(e) for all 8 batches ----------------
__global__ void __launch_bounds__(256) k_scatter(const int* __restrict__ src,
                                                 const int* __restrict__ dst,
                                                 const float* __restrict__ ew) {
    int e = blockIdx.x * blockDim.x + threadIdx.x;
    int s = src[e];
    int d = dst[e];
    float w = ew[e];
    int pos = atomicAdd(&d_cursor[s], 1);

    float4 a0 = *reinterpret_cast<const float4*>(&d_ssrcT[s * 8]);
    float4 a1 = *reinterpret_cast<const float4*>(&d_ssrcT[s * 8 + 4]);
    float4 b0 = *reinterpret_cast<const float4*>(&d_sdstT[d * 8]);
    float4 b1 = *reinterpret_cast<const float4*>(&d_sdstT[d * 8 + 4]);

    float4 e0, e1;
    #define LRW(x) ((x) > 0.f ? (x) : ALPHA * (x))
    e0.x = __expf(LRW(a0.x + b0.x) * w);
    e0.y = __expf(LRW(a0.y + b0.y) * w);
    e0.z = __expf(LRW(a0.z + b0.z) * w);
    e0.w = __expf(LRW(a0.w + b0.w) * w);
    e1.x = __expf(LRW(a1.x + b1.x) * w);
    e1.y = __expf(LRW(a1.y + b1.y) * w);
    e1.z = __expf(LRW(a1.z + b1.z) * w);
    e1.w = __expf(LRW(a1.w + b1.w) * w);
    #undef LRW

    d_dstP[pos] = d;
    *reinterpret_cast<float4*>(&d_exP[pos * 8])     = e0;
    *reinterpret_cast<float4*>(&d_exP[pos * 8 + 4]) = e1;
}

// ---------------- node kernel: one block per src node, sync-free main loop ----------------
// warp b handles batch b; all lanes accumulate the identical denominator, so no
// reduction/shared memory is needed at all.
__global__ void __launch_bounds__(256) k_node(float* __restrict__ out) {
    int n = blockIdx.x;
    int t = threadIdx.x;
    int beg = d_offsets[n];
    int end = d_offsets[n + 1];
    int b = t >> 5;
    int f2 = t & 31;

    if (beg == end) {
        int o = (b * Nn + n) * 64 + 2 * f2;
        out[o] = 0.f;
        out[o + 1] = 0.f;
        return;
    }

    const __half2* WhB = reinterpret_cast<const __half2*>(d_WhH) + (size_t)b * Nn * 32 + f2;
    float2 acc = make_float2(0.f, 0.f);
    float den = 0.f;

    int j = beg;
    for (; j + 4 <= end; j += 4) {
        int dv0 = d_dstP[j];
        int dv1 = d_dstP[j + 1];
        int dv2 = d_dstP[j + 2];
        int dv3 = d_dstP[j + 3];
        float w0 = d_exP[(size_t)j * 8 + b];
        float w1 = d_exP[(size_t)(j + 1) * 8 + b];
        float w2 = d_exP[(size_t)(j + 2) * 8 + b];
        float w3 = d_exP[(size_t)(j + 3) * 8 + b];
        __half2 v0 = WhB[(size_t)dv0 * 32];
        __half2 v1 = WhB[(size_t)dv1 * 32];
        __half2 v2 = WhB[(size_t)dv2 * 32];
        __half2 v3 = WhB[(size_t)dv3 * 32];
        den += (w0 + w1) + (w2 + w3);
        float2 f0 = __half22float2(v0);
        float2 f1 = __half22float2(v1);
        float2 f2v = __half22float2(v2);
        float2 f3 = __half22float2(v3);
        acc.x = fmaf(w0, f0.x, acc.x);  acc.y = fmaf(w0, f0.y, acc.y);
        acc.x = fmaf(w1, f1.x, acc.x);  acc.y = fmaf(w1, f1.y, acc.y);
        acc.x = fmaf(w2, f2v.x, acc.x); acc.y = fmaf(w2, f2v.y, acc.y);
        acc.x = fmaf(w3, f3.x, acc.x);  acc.y = fmaf(w3, f3.y, acc.y);
    }
    for (; j < end; j++) {
        int dv = d_dstP[j];
        float w = d_exP[(size_t)j * 8 + b];
        float2 v = __half22float2(WhB[(size_t)dv * 32]);
        den += w;
        acc.x = fmaf(w, v.x, acc.x);
        acc.y = fmaf(w, v.y, acc.y);
    }

    float inv = 1.f / den;
    float hp0 = acc.x * inv;
    float hp1 = acc.y * inv;
    int o = (b * Nn + n) * 64 + 2 * f2;
    out[o]     = hp0 > 0.f ? hp0 : expm1f(hp0);
    out[o + 1] = hp1 > 0.f ? hp1 : expm1f(hp1);
}

// ---------------- launch ----------------
extern "C" void kernel_launch(void* const* d_in, const int* in_sizes, int n_in,
                              void* d_out, int out_size) {
    const float* h  = (const float*)d_in[0];
    const int*   ei = (const int*)d_in[1];     // [2, E]: src then dst
    const float* ew = (const float*)d_in[2];
    const float* W  = (const float*)d_in[3];
    const float* a  = (const float*)d_in[4];
    float* out = (float*)d_out;

    const int* src = ei;
    const int* dst = ei + En;

    k_gemm_count<<<384, 256>>>(h, W, a, src);
    k_scan<<<1, 1024>>>();
    k_scatter<<<En / 256, 256>>>(src, dst, ew);
    k_node<<<Nn, 256>>>(out);
}

// round 4
// speedup vs baseline: 1.2106x; 1.2106x over previous
#include <cuda_runtime.h>
#include <cuda_fp16.h>
#include <math.h>

#define Bn 8
#define Nn 4096
#define En 131072
#define ALPHA 0.2f

// ---------------- device scratch (no allocations allowed) ----------------
__device__ __half d_WhH[Bn * Nn * 64];   // 4 MB, (b*N+n)*64+f, fp16
__device__ float  d_ssrcT[Nn * Bn];      // [n][b]
__device__ float  d_sdstT[Nn * Bn];      // [n][b]
__device__ int    d_counts[Nn];          // zero at load; re-zeroed by k_scan each launch
__device__ int    d_offsets[Nn + 1];
__device__ int    d_cursor[Nn];
__device__ int    d_dstP[En];            // dst in CSR order
__device__ float  d_exP[Bn * En];        // exp(e), batch-major planes [b][pos]

// ---------------- kernel 1: gemm (blocks 0..255) + degree count (blocks 256..383) ----------------
__global__ void __launch_bounds__(256) k_gemm_count(const float* __restrict__ h,
                                                    const float* __restrict__ W,
                                                    const float* __restrict__ a,
                                                    const int* __restrict__ src) {
    int t = threadIdx.x;
    if (blockIdx.x >= 256) {
        int base = (blockIdx.x - 256) * 1024 + t;
        #pragma unroll
        for (int k = 0; k < 4; k++)
            atomicAdd(&d_counts[src[base + k * 256]], 1);
        return;
    }

    __shared__ float sW[64 * 64];
    __shared__ float sh[4][64];
    __shared__ float red1[8], red2[8];

    for (int i = t; i < 4096; i += 256) sW[i] = W[i];
    __syncthreads();

    int g = t >> 6;        // row slot 0..3
    int o = t & 63;        // output feature

    // cache this thread's W column in registers (conflict-free scalar LDS)
    float wreg[64];
    #pragma unroll
    for (int f = 0; f < 64; f++) wreg[f] = sW[f * 64 + o];

    float a1r = a[o];
    float a2r = a[64 + o];
    int base = blockIdx.x * 128;

    for (int r0 = 0; r0 < 128; r0 += 4) {
        int row = base + r0 + g;   // b*N+n
        sh[g][o] = h[row * 64 + o];
        __syncthreads();
        float acc = 0.f;
        #pragma unroll
        for (int f = 0; f < 64; f += 4) {
            float4 hh = *reinterpret_cast<const float4*>(&sh[g][f]);
            acc = fmaf(hh.x, wreg[f],     acc);
            acc = fmaf(hh.y, wreg[f + 1], acc);
            acc = fmaf(hh.z, wreg[f + 2], acc);
            acc = fmaf(hh.w, wreg[f + 3], acc);
        }
        d_WhH[row * 64 + o] = __float2half(acc);

        float p1 = acc * a1r;
        float p2 = acc * a2r;
        #pragma unroll
        for (int off = 16; off; off >>= 1) {
            p1 += __shfl_xor_sync(0xffffffffu, p1, off);
            p2 += __shfl_xor_sync(0xffffffffu, p2, off);
        }
        int w = t >> 5;
        if ((t & 31) == 0) { red1[w] = p1; red2[w] = p2; }
        __syncthreads();
        if ((t & 63) == 0) {
            int b = row >> 12;
            int n = row & 4095;
            d_ssrcT[n * 8 + b] = red1[g * 2] + red1[g * 2 + 1];
            d_sdstT[n * 8 + b] = red2[g * 2] + red2[g * 2 + 1];
        }
        __syncthreads();
    }
}

// ---------------- scan: offsets from counts, then re-zero counts ----------------
__global__ void __launch_bounds__(1024) k_scan() {
    __shared__ int warp_sums[32];
    int t = threadIdx.x;
    int lane = t & 31, wid = t >> 5;
    int4 c = reinterpret_cast<const int4*>(d_counts)[t];
    reinterpret_cast<int4*>(d_counts)[t] = make_int4(0, 0, 0, 0);
    int sum = c.x + c.y + c.z + c.w;

    int v = sum;
    #pragma unroll
    for (int off = 1; off < 32; off <<= 1) {
        int u = __shfl_up_sync(0xffffffffu, v, off);
        if (lane >= off) v += u;
    }
    if (lane == 31) warp_sums[wid] = v;
    __syncthreads();
    if (wid == 0) {
        int w = warp_sums[lane];
        #pragma unroll
        for (int off = 1; off < 32; off <<= 1) {
            int u = __shfl_up_sync(0xffffffffu, w, off);
            if (lane >= off) w += u;
        }
        warp_sums[lane] = w;
    }
    __syncthreads();

    int base = (v - sum) + (wid ? warp_sums[wid - 1] : 0);
    int o0 = base;
    int o1 = base + c.x;
    int o2 = o1 + c.y;
    int o3 = o2 + c.z;
    d_offsets[4 * t + 0] = o0;  d_cursor[4 * t + 0] = o0;
    d_offsets[4 * t + 1] = o1;  d_cursor[4 * t + 1] = o1;
    d_offsets[4 * t + 2] = o2;  d_cursor[4 * t + 2] = o2;
    d_offsets[4 * t + 3] = o3;  d_cursor[4 * t + 3] = o3;
    if (t == 1023) d_offsets[Nn] = warp_sums[31];
}

// ---------------- scatter: permute + compute exp(e); writes batch-major planes ----------------
__global__ void __launch_bounds__(256) k_scatter(const int* __restrict__ src,
                                                 const int* __restrict__ dst,
                                                 const float* __restrict__ ew) {
    int e = blockIdx.x * blockDim.x + threadIdx.x;
    int s = src[e];
    int d = dst[e];
    float w = ew[e];
    int pos = atomicAdd(&d_cursor[s], 1);

    float4 a0 = *reinterpret_cast<const float4*>(&d_ssrcT[s * 8]);
    float4 a1 = *reinterpret_cast<const float4*>(&d_ssrcT[s * 8 + 4]);
    float4 b0 = *reinterpret_cast<const float4*>(&d_sdstT[d * 8]);
    float4 b1 = *reinterpret_cast<const float4*>(&d_sdstT[d * 8 + 4]);

    #define LRW(x) ((x) > 0.f ? (x) : ALPHA * (x))
    d_dstP[pos] = d;
    d_exP[0 * En + pos] = __expf(LRW(a0.x + b0.x) * w);
    d_exP[1 * En + pos] = __expf(LRW(a0.y + b0.y) * w);
    d_exP[2 * En + pos] = __expf(LRW(a0.z + b0.z) * w);
    d_exP[3 * En + pos] = __expf(LRW(a0.w + b0.w) * w);
    d_exP[4 * En + pos] = __expf(LRW(a1.x + b1.x) * w);
    d_exP[5 * En + pos] = __expf(LRW(a1.y + b1.y) * w);
    d_exP[6 * En + pos] = __expf(LRW(a1.z + b1.z) * w);
    d_exP[7 * En + pos] = __expf(LRW(a1.w + b1.w) * w);
    #undef LRW
}

// ---------------- node kernel: one block per src node, sync-free, 32-bit addressing ----------------
__global__ void __launch_bounds__(256) k_node(float* __restrict__ out) {
    int n = blockIdx.x;
    int t = threadIdx.x;
    int beg = d_offsets[n];
    int end = d_offsets[n + 1];
    int b = t >> 5;
    int f2 = t & 31;
    int o = (b * Nn + n) * 64 + 2 * f2;

    if (beg == end) {
        out[o] = 0.f;
        out[o + 1] = 0.f;
        return;
    }

    const __half2* __restrict__ WhB =
        reinterpret_cast<const __half2*>(d_WhH) + (unsigned)(b * (Nn * 32) + f2);
    const float* __restrict__ exb = d_exP + (unsigned)(b * En);
    float2 acc = make_float2(0.f, 0.f);
    float den = 0.f;

    int j = beg;
    int pe = (beg + 3) & ~3;          // peel to 16B alignment
    if (pe > end) pe = end;
    for (; j < pe; j++) {
        int dv = d_dstP[j];
        float w = exb[j];
        float2 v = __half22float2(WhB[(unsigned)dv * 32u]);
        den += w;
        acc.x = fmaf(w, v.x, acc.x);
        acc.y = fmaf(w, v.y, acc.y);
    }
    for (; j + 4 <= end; j += 4) {
        int4  dv = *reinterpret_cast<const int4*>(&d_dstP[j]);
        float4 w = *reinterpret_cast<const float4*>(&exb[j]);
        __half2 v0 = WhB[(unsigned)dv.x * 32u];
        __half2 v1 = WhB[(unsigned)dv.y * 32u];
        __half2 v2 = WhB[(unsigned)dv.z * 32u];
        __half2 v3 = WhB[(unsigned)dv.w * 32u];
        den += (w.x + w.y) + (w.z + w.w);
        float2 f0 = __half22float2(v0);
        float2 f1 = __half22float2(v1);
        float2 f2v = __half22float2(v2);
        float2 f3 = __half22float2(v3);
        acc.x = fmaf(w.x, f0.x, acc.x);  acc.y = fmaf(w.x, f0.y, acc.y);
        acc.x = fmaf(w.y, f1.x, acc.x);  acc.y = fmaf(w.y, f1.y, acc.y);
        acc.x = fmaf(w.z, f2v.x, acc.x); acc.y = fmaf(w.z, f2v.y, acc.y);
        acc.x = fmaf(w.w, f3.x, acc.x);  acc.y = fmaf(w.w, f3.y, acc.y);
    }
    for (; j < end; j++) {
        int dv = d_dstP[j];
        float w = exb[j];
        float2 v = __half22float2(WhB[(unsigned)dv * 32u]);
        den += w;
        acc.x = fmaf(w, v.x, acc.x);
        acc.y = fmaf(w, v.y, acc.y);
    }

    float inv = 1.f / den;
    float hp0 = acc.x * inv;
    float hp1 = acc.y * inv;
    out[o]     = hp0 > 0.f ? hp0 : expm1f(hp0);
    out[o + 1] = hp1 > 0.f ? hp1 : expm1f(hp1);
}

// ---------------- launch ----------------
extern "C" void kernel_launch(void* const* d_in, const int* in_sizes, int n_in,
                              void* d_out, int out_size) {
    const float* h  = (const float*)d_in[0];
    const int*   ei = (const int*)d_in[1];     // [2, E]: src then dst
    const float* ew = (const float*)d_in[2];
    const float* W  = (const float*)d_in[3];
    const float* a  = (const float*)d_in[4];
    float* out = (float*)d_out;

    const int* src = ei;
    const int* dst = ei + En;

    k_gemm_count<<<384, 256>>>(h, W, a, src);
    k_scan<<<1, 1024>>>();
    k_scatter<<<En / 256, 256>>>(src, dst, ew);
    k_node<<<Nn, 256>>>(out);
}

// round 5
// speedup vs baseline: 1.2473x; 1.0303x over previous
#include <cuda_runtime.h>
#include <math.h>

#define Bn 8
#define Nn 4096
#define En 131072
#define ALPHA 0.2f

// ---------------- device scratch (no allocations allowed) ----------------
__device__ float d_Wh[Bn * Nn * 64];    // 8 MB, [b][n][f] fp32
__device__ float d_ssrcT[Nn * Bn];      // [n][b]
__device__ float d_sdstT[Nn * Bn];      // [n][b]
__device__ int   d_counts[Nn];          // zero at load; re-zeroed by k_scan each launch
__device__ int   d_offsets[Nn + 1];
__device__ int   d_cursor[Nn];
__device__ int   d_srcP[En];            // src in CSR order
__device__ int   d_dstP[En];            // dst in CSR order
__device__ float d_ewP[En];             // edge weight in CSR order
__device__ float d_exP[Bn * En];        // exp(e), batch-major planes [b][pos]

// ---------------- kernel 1: gemm (blocks 0..255) + degree count (blocks 256..383) ----------------
__global__ void __launch_bounds__(256) k_gemm_count(const float* __restrict__ h,
                                                    const float* __restrict__ W,
                                                    const float* __restrict__ a,
                                                    const int* __restrict__ src) {
    int t = threadIdx.x;
    if (blockIdx.x >= 256) {
        int base = (blockIdx.x - 256) * 1024 + t;
        #pragma unroll
        for (int k = 0; k < 4; k++)
            atomicAdd(&d_counts[src[base + k * 256]], 1);
        return;
    }

    __shared__ float sW[64 * 64];
    __shared__ float sh[4][64];
    __shared__ float red1[8], red2[8];

    for (int i = t; i < 4096; i += 256) sW[i] = W[i];
    __syncthreads();

    int g = t >> 6;        // row slot 0..3
    int o = t & 63;        // output feature

    float wreg[64];
    #pragma unroll
    for (int f = 0; f < 64; f++) wreg[f] = sW[f * 64 + o];

    float a1r = a[o];
    float a2r = a[64 + o];
    int base = blockIdx.x * 128;

    for (int r0 = 0; r0 < 128; r0 += 4) {
        int row = base + r0 + g;   // b*N+n
        sh[g][o] = h[row * 64 + o];
        __syncthreads();
        float acc = 0.f;
        #pragma unroll
        for (int f = 0; f < 64; f += 4) {
            float4 hh = *reinterpret_cast<const float4*>(&sh[g][f]);
            acc = fmaf(hh.x, wreg[f],     acc);
            acc = fmaf(hh.y, wreg[f + 1], acc);
            acc = fmaf(hh.z, wreg[f + 2], acc);
            acc = fmaf(hh.w, wreg[f + 3], acc);
        }
        d_Wh[row * 64 + o] = acc;

        float p1 = acc * a1r;
        float p2 = acc * a2r;
        #pragma unroll
        for (int off = 16; off; off >>= 1) {
            p1 += __shfl_xor_sync(0xffffffffu, p1, off);
            p2 += __shfl_xor_sync(0xffffffffu, p2, off);
        }
        int w = t >> 5;
        if ((t & 31) == 0) { red1[w] = p1; red2[w] = p2; }
        __syncthreads();
        if ((t & 63) == 0) {
            int b = row >> 12;
            int n = row & 4095;
            d_ssrcT[n * 8 + b] = red1[g * 2] + red1[g * 2 + 1];
            d_sdstT[n * 8 + b] = red2[g * 2] + red2[g * 2 + 1];
        }
        __syncthreads();
    }
}

// ---------------- scan: offsets from counts, then re-zero counts ----------------
__global__ void __launch_bounds__(1024) k_scan() {
    __shared__ int warp_sums[32];
    int t = threadIdx.x;
    int lane = t & 31, wid = t >> 5;
    int4 c = reinterpret_cast<const int4*>(d_counts)[t];
    reinterpret_cast<int4*>(d_counts)[t] = make_int4(0, 0, 0, 0);
    int sum = c.x + c.y + c.z + c.w;

    int v = sum;
    #pragma unroll
    for (int off = 1; off < 32; off <<= 1) {
        int u = __shfl_up_sync(0xffffffffu, v, off);
        if (lane >= off) v += u;
    }
    if (lane == 31) warp_sums[wid] = v;
    __syncthreads();
    if (wid == 0) {
        int w = warp_sums[lane];
        #pragma unroll
        for (int off = 1; off < 32; off <<= 1) {
            int u = __shfl_up_sync(0xffffffffu, w, off);
            if (lane >= off) w += u;
        }
        warp_sums[lane] = w;
    }
    __syncthreads();

    int base = (v - sum) + (wid ? warp_sums[wid - 1] : 0);
    int o0 = base;
    int o1 = base + c.x;
    int o2 = o1 + c.y;
    int o3 = o2 + c.z;
    d_offsets[4 * t + 0] = o0;  d_cursor[4 * t + 0] = o0;
    d_offsets[4 * t + 1] = o1;  d_cursor[4 * t + 1] = o1;
    d_offsets[4 * t + 2] = o2;  d_cursor[4 * t + 2] = o2;
    d_offsets[4 * t + 3] = o3;  d_cursor[4 * t + 3] = o3;
    if (t == 1023) d_offsets[Nn] = warp_sums[31];
}

// ---------------- scatter: permutation only (3 scattered stores) ----------------
__global__ void __launch_bounds__(256) k_scatter(const int* __restrict__ src,
                                                 const int* __restrict__ dst,
                                                 const float* __restrict__ ew) {
    int e = blockIdx.x * blockDim.x + threadIdx.x;
    int s = src[e];
    int pos = atomicAdd(&d_cursor[s], 1);
    d_srcP[pos] = s;
    d_dstP[pos] = dst[e];
    d_ewP[pos]  = ew[e];
}

// ---------------- exp: pos-major, coalesced reads/writes, random 32B gathers ----------------
__global__ void __launch_bounds__(256) k_exp() {
    int pos = blockIdx.x * blockDim.x + threadIdx.x;
    int s = d_srcP[pos];
    int d = d_dstP[pos];
    float w = d_ewP[pos];

    float4 a0 = *reinterpret_cast<const float4*>(&d_ssrcT[s * 8]);
    float4 a1 = *reinterpret_cast<const float4*>(&d_ssrcT[s * 8 + 4]);
    float4 b0 = *reinterpret_cast<const float4*>(&d_sdstT[d * 8]);
    float4 b1 = *reinterpret_cast<const float4*>(&d_sdstT[d * 8 + 4]);

    #define LRW(x) ((x) > 0.f ? (x) : ALPHA * (x))
    d_exP[0 * En + pos] = __expf(LRW(a0.x + b0.x) * w);
    d_exP[1 * En + pos] = __expf(LRW(a0.y + b0.y) * w);
    d_exP[2 * En + pos] = __expf(LRW(a0.z + b0.z) * w);
    d_exP[3 * En + pos] = __expf(LRW(a0.w + b0.w) * w);
    d_exP[4 * En + pos] = __expf(LRW(a1.x + b1.x) * w);
    d_exP[5 * En + pos] = __expf(LRW(a1.y + b1.y) * w);
    d_exP[6 * En + pos] = __expf(LRW(a1.z + b1.z) * w);
    d_exP[7 * En + pos] = __expf(LRW(a1.w + b1.w) * w);
    #undef LRW
}

// ---------------- node kernel: one block per src node, sync-free, fp32 Wh ----------------
__global__ void __launch_bounds__(256) k_node(float* __restrict__ out) {
    int n = blockIdx.x;
    int t = threadIdx.x;
    int beg = d_offsets[n];
    int end = d_offsets[n + 1];
    int b = t >> 5;
    int f2 = t & 31;
    int o = (b * Nn + n) * 64 + 2 * f2;

    if (beg == end) {
        *reinterpret_cast<float2*>(&out[o]) = make_float2(0.f, 0.f);
        return;
    }

    const float2* __restrict__ WhB =
        reinterpret_cast<const float2*>(d_Wh) + (unsigned)(b * (Nn * 32) + f2);
    const float* __restrict__ exb = d_exP + (unsigned)(b * En);
    float ax0 = 0.f, ay0 = 0.f, ax1 = 0.f, ay1 = 0.f;
    float den0 = 0.f, den1 = 0.f;

    int j = beg;
    int pe = (beg + 3) & ~3;          // peel to 16B alignment
    if (pe > end) pe = end;
    for (; j < pe; j++) {
        int dv = d_dstP[j];
        float w = exb[j];
        float2 v = WhB[(unsigned)dv * 32u];
        den0 += w;
        ax0 = fmaf(w, v.x, ax0);
        ay0 = fmaf(w, v.y, ay0);
    }
    for (; j + 4 <= end; j += 4) {
        int4  dv = *reinterpret_cast<const int4*>(&d_dstP[j]);
        float4 w = *reinterpret_cast<const float4*>(&exb[j]);
        float2 v0 = WhB[(unsigned)dv.x * 32u];
        float2 v1 = WhB[(unsigned)dv.y * 32u];
        float2 v2 = WhB[(unsigned)dv.z * 32u];
        float2 v3 = WhB[(unsigned)dv.w * 32u];
        den0 += (w.x + w.y);
        den1 += (w.z + w.w);
        ax0 = fmaf(w.x, v0.x, ax0);  ay0 = fmaf(w.x, v0.y, ay0);
        ax1 = fmaf(w.y, v1.x, ax1);  ay1 = fmaf(w.y, v1.y, ay1);
        ax0 = fmaf(w.z, v2.x, ax0);  ay0 = fmaf(w.z, v2.y, ay0);
        ax1 = fmaf(w.w, v3.x, ax1);  ay1 = fmaf(w.w, v3.y, ay1);
    }
    for (; j < end; j++) {
        int dv = d_dstP[j];
        float w = exb[j];
        float2 v = WhB[(unsigned)dv * 32u];
        den0 += w;
        ax0 = fmaf(w, v.x, ax0);
        ay0 = fmaf(w, v.y, ay0);
    }

    float inv = 1.f / (den0 + den1);
    float hp0 = (ax0 + ax1) * inv;
    float hp1 = (ay0 + ay1) * inv;
    float2 res;
    res.x = hp0 > 0.f ? hp0 : expm1f(hp0);
    res.y = hp1 > 0.f ? hp1 : expm1f(hp1);
    *reinterpret_cast<float2*>(&out[o]) = res;
}

// ---------------- launch ----------------
extern "C" void kernel_launch(void* const* d_in, const int* in_sizes, int n_in,
                              void* d_out, int out_size) {
    const float* h  = (const float*)d_in[0];
    const int*   ei = (const int*)d_in[1];     // [2, E]: src then dst
    const float* ew = (const float*)d_in[2];
    const float* W  = (const float*)d_in[3];
    const float* a  = (const float*)d_in[4];
    float* out = (float*)d_out;

    const int* src = ei;
    const int* dst = ei + En;

    k_gemm_count<<<384, 256>>>(h, W, a, src);
    k_scan<<<1, 1024>>>();
    k_scatter<<<En / 256, 256>>>(src, dst, ew);
    k_exp<<<En / 256, 256>>>();
    k_node<<<Nn, 256>>>(out);
}